// round 2
// baseline (speedup 1.0000x reference)
#include <cuda_runtime.h>
#include <math.h>

// Problem constants
#define BB   64
#define TT   366
#define INF  24
#define H1   1024
#define H2   2048
#define HM   2048
#define PEN  1024
#define BT   23424      // BB*TT
#define G3   6144       // 3*HM

// ---------------------------------------------------------------------------
// Scratch (allocation-free: __device__ globals)
// ---------------------------------------------------------------------------
__device__ float g_act1[(size_t)BT * H1];            //  96 MB
__device__ float g_act2[(size_t)BT * H2];            // 192 MB
__device__ float g_xg  [(size_t)BT * G3];            // 576 MB
__device__ float g_hs  [(size_t)(TT + 1) * BB * HM]; // 192 MB (slot 0 = h0 = 0)
__device__ float g_outs[(size_t)BT * PEN];           //  96 MB
__device__ int   g_labels[BB];

// ---------------------------------------------------------------------------
// Label decode: dtype-robust (int32 vs int64 little-endian).
// If the buffer is int64 with values in [0,21), every odd int32 word is 0.
// ---------------------------------------------------------------------------
__global__ void decode_labels_kernel(const int* __restrict__ raw)
{
    __shared__ int any_odd_nonzero;
    if (threadIdx.x == 0) any_odd_nonzero = 0;
    __syncthreads();
    // check odd int32 words among the first 64 (safe for both dtypes)
    if (threadIdx.x < 32) {
        if (raw[2 * threadIdx.x + 1] != 0) atomicOr(&any_odd_nonzero, 1);
    }
    __syncthreads();
    const bool is64 = (any_odd_nonzero == 0);
    if (threadIdx.x < BB) {
        g_labels[threadIdx.x] = is64 ? raw[2 * threadIdx.x] : raw[threadIdx.x];
    }
}

// ---------------------------------------------------------------------------
// Generic NT GEMM: C[M,N] = act(A[M,K] @ B[N,K]^T + bias[N])
// Requires M%128==0, N%128==0, K%8==0. 128x128x8 tiles, 256 thr, 8x8 microtile.
// ---------------------------------------------------------------------------
template<bool RELU>
__global__ __launch_bounds__(256) void gemm_nt(
    const float* __restrict__ A, const float* __restrict__ Bm,
    const float* __restrict__ bias, float* __restrict__ C,
    int M, int N, int K)
{
    __shared__ float As[8][128];
    __shared__ float Bs[8][128];

    const int tid  = threadIdx.x;
    const int tx   = tid & 15;       // N dir (x8)
    const int ty   = tid >> 4;       // M dir (x8)
    const int arow = tid >> 1;       // 0..127
    const int acol = (tid & 1) << 2; // 0 or 4

    const float* Ap = A  + (size_t)(blockIdx.y * 128 + arow) * K + acol;
    const float* Bp = Bm + (size_t)(blockIdx.x * 128 + arow) * K + acol;

    float acc[8][8];
#pragma unroll
    for (int i = 0; i < 8; i++)
#pragma unroll
        for (int j = 0; j < 8; j++) acc[i][j] = 0.0f;

    for (int k0 = 0; k0 < K; k0 += 8) {
        float4 a = *(const float4*)(Ap + k0);
        float4 b = *(const float4*)(Bp + k0);
        __syncthreads();
        As[acol + 0][arow] = a.x; As[acol + 1][arow] = a.y;
        As[acol + 2][arow] = a.z; As[acol + 3][arow] = a.w;
        Bs[acol + 0][arow] = b.x; Bs[acol + 1][arow] = b.y;
        Bs[acol + 2][arow] = b.z; Bs[acol + 3][arow] = b.w;
        __syncthreads();
#pragma unroll
        for (int k = 0; k < 8; k++) {
            float av[8], bv[8];
            *(float4*)(av)     = *(const float4*)&As[k][ty * 8];
            *(float4*)(av + 4) = *(const float4*)&As[k][ty * 8 + 4];
            *(float4*)(bv)     = *(const float4*)&Bs[k][tx * 8];
            *(float4*)(bv + 4) = *(const float4*)&Bs[k][tx * 8 + 4];
#pragma unroll
            for (int i = 0; i < 8; i++)
#pragma unroll
                for (int j = 0; j < 8; j++)
                    acc[i][j] += av[i] * bv[j];
        }
    }

    const int crow = blockIdx.y * 128 + ty * 8;
    const int ccol = blockIdx.x * 128 + tx * 8;
#pragma unroll
    for (int i = 0; i < 8; i++) {
#pragma unroll
        for (int j = 0; j < 8; j++) {
            float v = acc[i][j] + bias[ccol + j];
            if (RELU) v = fmaxf(v, 0.0f);
            C[(size_t)(crow + i) * N + ccol + j] = v;
        }
    }
}

// ---------------------------------------------------------------------------
// GRU step: one kernel per timestep. Each block owns 16 hidden units,
// computes hr/hz/hn (GEMM vs h_prev, K=2048) and fuses the gate update.
// Grid = 128 blocks, 256 threads. Reads hs[t], writes hs[t+1].
// ---------------------------------------------------------------------------
#define GHT 16   // hidden units per block
#define GKT 16   // K tile

__global__ __launch_bounds__(256) void gru_step_kernel(
    const float* __restrict__ hprev,   // [BB][HM]
    float*       __restrict__ hout,    // [BB][HM]
    const float* __restrict__ xg,      // [BT][G3], row = b*TT + t (incl. b_ih)
    const float* __restrict__ W_hh,    // [G3][HM]
    const float* __restrict__ b_hh,    // [G3]
    int t)
{
    __shared__ float Hs[GKT][BB];        // h tile, [k][b]
    __shared__ float Ws[GKT][3 * GHT];   // W tile, [k][gate*GHT+u]

    const int tid = threadIdx.x;
    const int tx  = tid & 15;   // hidden unit in block (0..15)
    const int ty  = tid >> 4;   // batch group (0..15), 4 batches each
    const int n0  = blockIdx.x * GHT;

    float ar[4] = {0, 0, 0, 0}, az[4] = {0, 0, 0, 0}, an[4] = {0, 0, 0, 0};

    const int lb = tid >> 2;         // batch row for H load (0..63)
    const int lk = (tid & 3) << 2;   // k offset 0,4,8,12

    for (int k0 = 0; k0 < HM; k0 += GKT) {
        __syncthreads();
        {
            float4 h4 = *(const float4*)&hprev[(size_t)lb * HM + k0 + lk];
            Hs[lk + 0][lb] = h4.x; Hs[lk + 1][lb] = h4.y;
            Hs[lk + 2][lb] = h4.z; Hs[lk + 3][lb] = h4.w;
        }
        // W tile: 48 rows x 16 k = 192 float4, threads 0..191
        if (tid < (3 * GHT) * (GKT / 4)) {
            const int r    = tid >> 2;          // 0..47
            const int kc   = (tid & 3) << 2;    // 0,4,8,12
            const int gate = r / GHT;
            const int u    = r % GHT;
            float4 w4 = *(const float4*)
                &W_hh[(size_t)(gate * HM + n0 + u) * HM + k0 + kc];
            Ws[kc + 0][r] = w4.x; Ws[kc + 1][r] = w4.y;
            Ws[kc + 2][r] = w4.z; Ws[kc + 3][r] = w4.w;
        }
        __syncthreads();
#pragma unroll
        for (int k = 0; k < GKT; k++) {
            float hv[4];
            *(float4*)hv = *(const float4*)&Hs[k][ty * 4];
            const float wr = Ws[k][tx];
            const float wz = Ws[k][GHT + tx];
            const float wn = Ws[k][2 * GHT + tx];
#pragma unroll
            for (int i = 0; i < 4; i++) {
                ar[i] += hv[i] * wr;
                az[i] += hv[i] * wz;
                an[i] += hv[i] * wn;
            }
        }
    }

    const int u = n0 + tx;
    const float bhr = b_hh[u];
    const float bhz = b_hh[HM + u];
    const float bhn = b_hh[2 * HM + u];
#pragma unroll
    for (int i = 0; i < 4; i++) {
        const int b = ty * 4 + i;
        const float* xrow = xg + (size_t)(b * TT + t) * G3;
        const float xr = xrow[u];
        const float xz = xrow[HM + u];
        const float xn = xrow[2 * HM + u];
        const float r  = 1.0f / (1.0f + expf(-(xr + ar[i] + bhr)));
        const float z  = 1.0f / (1.0f + expf(-(xz + az[i] + bhz)));
        const float nn = tanhf(xn + r * (an[i] + bhn));
        const float hp = hprev[(size_t)b * HM + u];
        hout[(size_t)b * HM + u] = (1.0f - z) * nn + z * hp;
    }
}

// ---------------------------------------------------------------------------
// Per-(b,t) heads: 3 dot products of length PEN against label-selected rows.
// One block per row r = t*BB + b of out_s (time-major).
// ---------------------------------------------------------------------------
__global__ __launch_bounds__(128) void heads_kernel(
    const float* __restrict__ outs,
    const float* __restrict__ W4, const float* __restrict__ b4,
    const float* __restrict__ W5, const float* __restrict__ b5,
    const float* __restrict__ W6, const float* __restrict__ b6,
    float* __restrict__ out)
{
    const int r  = blockIdx.x;     // t*BB + b
    const int t  = r >> 6;
    const int b  = r & 63;
    const int lab = g_labels[b];
    const float* s  = outs + (size_t)r * PEN;
    const float* w4 = W4 + (size_t)lab * PEN;
    const float* w5 = W5 + (size_t)lab * PEN;
    const float* w6 = W6 + (size_t)lab * PEN;

    float a4 = 0.f, a5 = 0.f, a6 = 0.f;
    for (int p = threadIdx.x; p < PEN; p += 128) {
        const float v = s[p];
        a4 += v * w4[p];
        a5 += v * w5[p];
        a6 += v * w6[p];
    }
    __shared__ float red[3][128];
    red[0][threadIdx.x] = a4;
    red[1][threadIdx.x] = a5;
    red[2][threadIdx.x] = a6;
    __syncthreads();
    for (int s2 = 64; s2 > 0; s2 >>= 1) {
        if (threadIdx.x < s2) {
            red[0][threadIdx.x] += red[0][threadIdx.x + s2];
            red[1][threadIdx.x] += red[1][threadIdx.x + s2];
            red[2][threadIdx.x] += red[2][threadIdx.x + s2];
        }
        __syncthreads();
    }
    if (threadIdx.x == 0) {
        const int o = b * TT + t;
        out[o]          = red[0][0] + b4[lab];
        out[BT + o]     = red[1][0] + b5[lab];
        out[2 * BT + o] = red[2][0] + b6[lab];
    }
}

__global__ void zero_kernel(float* p, int n)
{
    int i = blockIdx.x * blockDim.x + threadIdx.x;
    if (i < n) p[i] = 0.0f;
}

// ---------------------------------------------------------------------------
// Launch
// ---------------------------------------------------------------------------
extern "C" void kernel_launch(void* const* d_in, const int* in_sizes, int n_in,
                              void* d_out, int out_size)
{
    const float* x    = (const float*)d_in[0];
    const int*   labr = (const int*)d_in[1];
    const float* W1   = (const float*)d_in[2];
    const float* b1   = (const float*)d_in[3];
    const float* W2   = (const float*)d_in[4];
    const float* b2   = (const float*)d_in[5];
    const float* W_ih = (const float*)d_in[6];
    const float* W_hh = (const float*)d_in[7];
    const float* b_ih = (const float*)d_in[8];
    const float* b_hh = (const float*)d_in[9];
    const float* W3   = (const float*)d_in[10];
    const float* b3   = (const float*)d_in[11];
    const float* W4   = (const float*)d_in[12];
    const float* b4   = (const float*)d_in[13];
    const float* W5   = (const float*)d_in[14];
    const float* b5   = (const float*)d_in[15];
    const float* W6   = (const float*)d_in[16];
    const float* b6   = (const float*)d_in[17];
    float* out = (float*)d_out;

    float *act1, *act2, *xg, *hs, *outs;
    cudaGetSymbolAddress((void**)&act1, g_act1);
    cudaGetSymbolAddress((void**)&act2, g_act2);
    cudaGetSymbolAddress((void**)&xg,   g_xg);
    cudaGetSymbolAddress((void**)&hs,   g_hs);
    cudaGetSymbolAddress((void**)&outs, g_outs);

    // Decode labels (int32 vs int64 robust)
    decode_labels_kernel<<<1, 64>>>(labr);

    // h0 = 0
    zero_kernel<<<(BB * HM + 255) / 256, 256>>>(hs, BB * HM);
    // Zero the tail of d_out (the two scalar 0 outputs, if present)
    const int tail = out_size - 3 * BT;
    if (tail > 0)
        zero_kernel<<<(tail + 255) / 256, 256>>>(out + 3 * BT, tail);

    // act1 = relu(x @ W1^T + b1)           [BT, H1], K=24
    {
        dim3 g(H1 / 128, BT / 128);
        gemm_nt<true><<<g, 256>>>(x, W1, b1, act1, BT, H1, INF);
    }
    // act2 = relu(act1 @ W2^T + b2)        [BT, H2], K=1024
    {
        dim3 g(H2 / 128, BT / 128);
        gemm_nt<true><<<g, 256>>>(act1, W2, b2, act2, BT, H2, H1);
    }
    // xg = act2 @ W_ih^T + b_ih            [BT, 6144], K=2048
    {
        dim3 g(G3 / 128, BT / 128);
        gemm_nt<false><<<g, 256>>>(act2, W_ih, b_ih, xg, BT, G3, H2);
    }
    // GRU recurrence: hs[t] -> hs[t+1]
    for (int t = 0; t < TT; t++) {
        gru_step_kernel<<<HM / GHT, 256>>>(
            hs + (size_t)t * BB * HM,
            hs + (size_t)(t + 1) * BB * HM,
            xg, W_hh, b_hh, t);
    }
    // out_s = relu(hs[1..T] @ W3^T + b3)   [BT, PEN] (time-major rows)
    {
        dim3 g(PEN / 128, BT / 128);
        gemm_nt<true><<<g, 256>>>(hs + (size_t)BB * HM, W3, b3, outs, BT, PEN, H2);
    }
    // heads
    heads_kernel<<<BT, 128>>>(outs, W4, b4, W5, b5, W6, b6, out);
}

// round 3
// speedup vs baseline: 1.1586x; 1.1586x over previous
#include <cuda_runtime.h>
#include <math.h>
#include <stdint.h>

// Problem constants
#define BB   64
#define TT   366
#define INF  24
#define H1   1024
#define H2   2048
#define HM   2048
#define PEN  1024
#define BT   23424      // BB*TT
#define G3   6144       // 3*HM

// ---------------------------------------------------------------------------
// Scratch (allocation-free: __device__ globals)
// ---------------------------------------------------------------------------
__device__ float g_act1[(size_t)BT * H1];            //  96 MB
__device__ float g_act2[(size_t)BT * H2];            // 192 MB
__device__ float g_xg  [(size_t)BT * G3];            // 576 MB
__device__ float g_hs  [(size_t)(TT + 1) * BB * HM]; // 192 MB (slot 0 = h0 = 0)
__device__ float g_outs[(size_t)BT * PEN];           //  96 MB
__device__ float g_hg  [(size_t)BB * G3];            // 1.5 MB  gate pre-activations
__device__ float g_hhi [(size_t)BB * HM];            // h split hi (tf32-representable)
__device__ float g_hlo [(size_t)BB * HM];            // h split lo
__device__ int   g_labels[BB];

// ---------------------------------------------------------------------------
// tf32 helpers
// ---------------------------------------------------------------------------
__device__ __forceinline__ unsigned f2tf32(float x) {
    unsigned u;
    asm("cvt.rna.tf32.f32 %0, %1;" : "=r"(u) : "f"(x));
    return u;
}

__device__ __forceinline__ void mma_tf32(float* d, const unsigned* a, const unsigned* b) {
    asm volatile(
        "mma.sync.aligned.m16n8k8.row.col.f32.tf32.tf32.f32 "
        "{%0,%1,%2,%3}, {%4,%5,%6,%7}, {%8,%9}, {%0,%1,%2,%3};"
        : "+f"(d[0]), "+f"(d[1]), "+f"(d[2]), "+f"(d[3])
        : "r"(a[0]), "r"(a[1]), "r"(a[2]), "r"(a[3]), "r"(b[0]), "r"(b[1]));
}

#define TKP 36   // padded k-stride (words): bank = (4*row + k) % 32 -> lane, conflict-free

// ---------------------------------------------------------------------------
// Label decode: dtype-robust (int32 vs int64 little-endian).
// ---------------------------------------------------------------------------
__global__ void decode_labels_kernel(const int* __restrict__ raw)
{
    __shared__ int any_odd_nonzero;
    if (threadIdx.x == 0) any_odd_nonzero = 0;
    __syncthreads();
    if (threadIdx.x < 32) {
        if (raw[2 * threadIdx.x + 1] != 0) atomicOr(&any_odd_nonzero, 1);
    }
    __syncthreads();
    const bool is64 = (any_odd_nonzero == 0);
    if (threadIdx.x < BB) {
        g_labels[threadIdx.x] = is64 ? raw[2 * threadIdx.x] : raw[threadIdx.x];
    }
}

// ---------------------------------------------------------------------------
// TF32 tensor-core NT GEMM: C[M,N] = act(A[M,K] @ B[N,K]^T + bias[N])
// M%128==0, N%128==0, K%32==0. Block 128x128, 8 warps of m64xn32, K-tile 32.
// ---------------------------------------------------------------------------
template<bool RELU>
__global__ __launch_bounds__(256, 2) void gemm_tf32_nt(
    const float* __restrict__ A, const float* __restrict__ Bm,
    const float* __restrict__ bias, float* __restrict__ C,
    int M, int N, int K)
{
    __shared__ unsigned As[128 * TKP];
    __shared__ unsigned Bs[128 * TKP];

    const int tid  = threadIdx.x;
    const int lane = tid & 31;
    const int warp = tid >> 5;
    const int wm   = warp >> 2;   // 0..1 (64 rows each)
    const int wn   = warp & 3;    // 0..3 (32 cols each)
    const int g    = lane >> 2;   // groupID
    const int tg   = lane & 3;    // thread in group

    const int mBase = blockIdx.y * 128;
    const int nBase = blockIdx.x * 128;
    const int lrow  = tid >> 1;          // 0..127
    const int lcol  = (tid & 1) << 2;    // 0 or 4

    float acc[4][4][4];
#pragma unroll
    for (int i = 0; i < 4; i++)
#pragma unroll
        for (int j = 0; j < 4; j++)
#pragma unroll
            for (int q = 0; q < 4; q++) acc[i][j][q] = 0.0f;

    const float* Ap = A  + (size_t)(mBase + lrow) * K + lcol;
    const float* Bp = Bm + (size_t)(nBase + lrow) * K + lcol;

    for (int k0 = 0; k0 < K; k0 += 32) {
        __syncthreads();
#pragma unroll
        for (int p = 0; p < 4; p++) {
            float4 av = *(const float4*)(Ap + k0 + p * 8);
            float4 bv = *(const float4*)(Bp + k0 + p * 8);
            uint4 at = make_uint4(f2tf32(av.x), f2tf32(av.y), f2tf32(av.z), f2tf32(av.w));
            uint4 bt = make_uint4(f2tf32(bv.x), f2tf32(bv.y), f2tf32(bv.z), f2tf32(bv.w));
            *(uint4*)&As[lrow * TKP + p * 8 + lcol] = at;
            *(uint4*)&Bs[lrow * TKP + p * 8 + lcol] = bt;
        }
        __syncthreads();
#pragma unroll
        for (int kk = 0; kk < 32; kk += 8) {
            unsigned af[4][4], bf[4][2];
#pragma unroll
            for (int f = 0; f < 4; f++) {
                const int r = (wm * 64 + f * 16 + g) * TKP + kk + tg;
                af[f][0] = As[r];
                af[f][1] = As[r + 8 * TKP];
                af[f][2] = As[r + 4];
                af[f][3] = As[r + 8 * TKP + 4];
            }
#pragma unroll
            for (int f = 0; f < 4; f++) {
                const int r = (wn * 32 + f * 8 + g) * TKP + kk + tg;
                bf[f][0] = Bs[r];
                bf[f][1] = Bs[r + 4];
            }
#pragma unroll
            for (int i = 0; i < 4; i++)
#pragma unroll
                for (int j = 0; j < 4; j++)
                    mma_tf32(acc[i][j], af[i], bf[j]);
        }
    }

#pragma unroll
    for (int i = 0; i < 4; i++) {
        const int row = mBase + wm * 64 + i * 16 + g;
#pragma unroll
        for (int j = 0; j < 4; j++) {
            const int col = nBase + wn * 32 + j * 8 + tg * 2;
            const float b0 = bias[col], b1 = bias[col + 1];
            float v00 = acc[i][j][0] + b0, v01 = acc[i][j][1] + b1;
            float v10 = acc[i][j][2] + b0, v11 = acc[i][j][3] + b1;
            if (RELU) {
                v00 = fmaxf(v00, 0.0f); v01 = fmaxf(v01, 0.0f);
                v10 = fmaxf(v10, 0.0f); v11 = fmaxf(v11, 0.0f);
            }
            C[(size_t)row * N + col]           = v00;
            C[(size_t)row * N + col + 1]       = v01;
            C[(size_t)(row + 8) * N + col]     = v10;
            C[(size_t)(row + 8) * N + col + 1] = v11;
        }
    }
}

// ---------------------------------------------------------------------------
// GRU recurrent GEMM: HG[64, 6144] = (h_hi + h_lo) @ W_hh^T
// Split precision: both tf32 halves accumulate into the same fp32 acc,
// sharing B fragments. Grid 96 blocks (N-tile 64), block 128 thr (4 warps,
// 2x2 of m32xn32).
// ---------------------------------------------------------------------------
__global__ __launch_bounds__(128) void gru_gemm(
    const float* __restrict__ hhi, const float* __restrict__ hlo,
    const float* __restrict__ Whh, float* __restrict__ HG)
{
    __shared__ unsigned Ah[64 * TKP];
    __shared__ unsigned Al[64 * TKP];
    __shared__ unsigned Bs[64 * TKP];

    const int tid  = threadIdx.x;
    const int lane = tid & 31;
    const int warp = tid >> 5;
    const int wm   = warp >> 1;   // 0..1 (32 rows)
    const int wn   = warp & 1;    // 0..1 (32 cols)
    const int g    = lane >> 2;
    const int tg   = lane & 3;

    const int nBase = blockIdx.x * 64;
    const int lrow  = tid >> 1;          // 0..63
    const int lcol  = (tid & 1) << 2;

    float acc[2][4][4];
#pragma unroll
    for (int i = 0; i < 2; i++)
#pragma unroll
        for (int j = 0; j < 4; j++)
#pragma unroll
            for (int q = 0; q < 4; q++) acc[i][j][q] = 0.0f;

    const float* Hp = hhi + (size_t)lrow * HM + lcol;
    const float* Lp = hlo + (size_t)lrow * HM + lcol;
    const float* Wp = Whh + (size_t)(nBase + lrow) * HM + lcol;

    for (int k0 = 0; k0 < HM; k0 += 32) {
        __syncthreads();
#pragma unroll
        for (int p = 0; p < 4; p++) {
            float4 hv = *(const float4*)(Hp + k0 + p * 8);
            float4 lv = *(const float4*)(Lp + k0 + p * 8);
            float4 wv = *(const float4*)(Wp + k0 + p * 8);
            *(uint4*)&Ah[lrow * TKP + p * 8 + lcol] =
                make_uint4(f2tf32(hv.x), f2tf32(hv.y), f2tf32(hv.z), f2tf32(hv.w));
            *(uint4*)&Al[lrow * TKP + p * 8 + lcol] =
                make_uint4(f2tf32(lv.x), f2tf32(lv.y), f2tf32(lv.z), f2tf32(lv.w));
            *(uint4*)&Bs[lrow * TKP + p * 8 + lcol] =
                make_uint4(f2tf32(wv.x), f2tf32(wv.y), f2tf32(wv.z), f2tf32(wv.w));
        }
        __syncthreads();
#pragma unroll
        for (int kk = 0; kk < 32; kk += 8) {
            unsigned bf[4][2];
#pragma unroll
            for (int f = 0; f < 4; f++) {
                const int r = (wn * 32 + f * 8 + g) * TKP + kk + tg;
                bf[f][0] = Bs[r];
                bf[f][1] = Bs[r + 4];
            }
            unsigned af[2][4];
#pragma unroll
            for (int f = 0; f < 2; f++) {
                const int r = (wm * 32 + f * 16 + g) * TKP + kk + tg;
                af[f][0] = Ah[r];
                af[f][1] = Ah[r + 8 * TKP];
                af[f][2] = Ah[r + 4];
                af[f][3] = Ah[r + 8 * TKP + 4];
            }
#pragma unroll
            for (int i = 0; i < 2; i++)
#pragma unroll
                for (int j = 0; j < 4; j++)
                    mma_tf32(acc[i][j], af[i], bf[j]);
#pragma unroll
            for (int f = 0; f < 2; f++) {
                const int r = (wm * 32 + f * 16 + g) * TKP + kk + tg;
                af[f][0] = Al[r];
                af[f][1] = Al[r + 8 * TKP];
                af[f][2] = Al[r + 4];
                af[f][3] = Al[r + 8 * TKP + 4];
            }
#pragma unroll
            for (int i = 0; i < 2; i++)
#pragma unroll
                for (int j = 0; j < 4; j++)
                    mma_tf32(acc[i][j], af[i], bf[j]);
        }
    }

#pragma unroll
    for (int i = 0; i < 2; i++) {
        const int row = wm * 32 + i * 16 + g;
#pragma unroll
        for (int j = 0; j < 4; j++) {
            const int col = nBase + wn * 32 + j * 8 + tg * 2;
            HG[(size_t)row * G3 + col]           = acc[i][j][0];
            HG[(size_t)row * G3 + col + 1]       = acc[i][j][1];
            HG[(size_t)(row + 8) * G3 + col]     = acc[i][j][2];
            HG[(size_t)(row + 8) * G3 + col + 1] = acc[i][j][3];
        }
    }
}

// ---------------------------------------------------------------------------
// GRU gate fusion: h_new from HG + xg; also emits tf32 hi/lo split of h_new.
// Grid 512 x 256 over 64*2048 elements.
// ---------------------------------------------------------------------------
__global__ __launch_bounds__(256) void gru_fuse(
    const float* __restrict__ HG, const float* __restrict__ xg,
    const float* __restrict__ hprev, const float* __restrict__ b_hh,
    float* __restrict__ hnew, float* __restrict__ hhi, float* __restrict__ hlo,
    int t)
{
    const int i = blockIdx.x * 256 + threadIdx.x;   // < 64*2048
    const int b = i >> 11;
    const int u = i & 2047;

    const float ar = HG[(size_t)b * G3 + u]          + b_hh[u];
    const float az = HG[(size_t)b * G3 + HM + u]     + b_hh[HM + u];
    const float an = HG[(size_t)b * G3 + 2 * HM + u] + b_hh[2 * HM + u];

    const float* xrow = xg + (size_t)(b * TT + t) * G3;
    const float r  = 1.0f / (1.0f + expf(-(xrow[u] + ar)));
    const float z  = 1.0f / (1.0f + expf(-(xrow[HM + u] + az)));
    const float nn = tanhf(xrow[2 * HM + u] + r * an);
    const float hp = hprev[i];
    const float h  = (1.0f - z) * nn + z * hp;

    hnew[i] = h;
    const float hi = __uint_as_float(f2tf32(h));
    hhi[i] = hi;
    hlo[i] = __uint_as_float(f2tf32(h - hi));
}

// ---------------------------------------------------------------------------
// FFMA GEMM (kept only for act1, K=24): C = relu(A@B^T + bias)
// ---------------------------------------------------------------------------
__global__ __launch_bounds__(256) void gemm_ffma_nt(
    const float* __restrict__ A, const float* __restrict__ Bm,
    const float* __restrict__ bias, float* __restrict__ C,
    int M, int N, int K)
{
    __shared__ float As[8][128];
    __shared__ float Bs[8][128];

    const int tid  = threadIdx.x;
    const int tx   = tid & 15;
    const int ty   = tid >> 4;
    const int arow = tid >> 1;
    const int acol = (tid & 1) << 2;

    const float* Ap = A  + (size_t)(blockIdx.y * 128 + arow) * K + acol;
    const float* Bp = Bm + (size_t)(blockIdx.x * 128 + arow) * K + acol;

    float acc[8][8];
#pragma unroll
    for (int i = 0; i < 8; i++)
#pragma unroll
        for (int j = 0; j < 8; j++) acc[i][j] = 0.0f;

    for (int k0 = 0; k0 < K; k0 += 8) {
        float4 a = *(const float4*)(Ap + k0);
        float4 b = *(const float4*)(Bp + k0);
        __syncthreads();
        As[acol + 0][arow] = a.x; As[acol + 1][arow] = a.y;
        As[acol + 2][arow] = a.z; As[acol + 3][arow] = a.w;
        Bs[acol + 0][arow] = b.x; Bs[acol + 1][arow] = b.y;
        Bs[acol + 2][arow] = b.z; Bs[acol + 3][arow] = b.w;
        __syncthreads();
#pragma unroll
        for (int k = 0; k < 8; k++) {
            float av[8], bv[8];
            *(float4*)(av)     = *(const float4*)&As[k][ty * 8];
            *(float4*)(av + 4) = *(const float4*)&As[k][ty * 8 + 4];
            *(float4*)(bv)     = *(const float4*)&Bs[k][tx * 8];
            *(float4*)(bv + 4) = *(const float4*)&Bs[k][tx * 8 + 4];
#pragma unroll
            for (int i = 0; i < 8; i++)
#pragma unroll
                for (int j = 0; j < 8; j++)
                    acc[i][j] += av[i] * bv[j];
        }
    }

    const int crow = blockIdx.y * 128 + ty * 8;
    const int ccol = blockIdx.x * 128 + tx * 8;
#pragma unroll
    for (int i = 0; i < 8; i++) {
#pragma unroll
        for (int j = 0; j < 8; j++) {
            float v = acc[i][j] + bias[ccol + j];
            v = fmaxf(v, 0.0f);
            C[(size_t)(crow + i) * N + ccol + j] = v;
        }
    }
}

// ---------------------------------------------------------------------------
// Per-(b,t) heads
// ---------------------------------------------------------------------------
__global__ __launch_bounds__(128) void heads_kernel(
    const float* __restrict__ outs,
    const float* __restrict__ W4, const float* __restrict__ b4,
    const float* __restrict__ W5, const float* __restrict__ b5,
    const float* __restrict__ W6, const float* __restrict__ b6,
    float* __restrict__ out)
{
    const int r  = blockIdx.x;     // t*BB + b
    const int t  = r >> 6;
    const int b  = r & 63;
    const int lab = g_labels[b];
    const float* s  = outs + (size_t)r * PEN;
    const float* w4 = W4 + (size_t)lab * PEN;
    const float* w5 = W5 + (size_t)lab * PEN;
    const float* w6 = W6 + (size_t)lab * PEN;

    float a4 = 0.f, a5 = 0.f, a6 = 0.f;
    for (int p = threadIdx.x; p < PEN; p += 128) {
        const float v = s[p];
        a4 += v * w4[p];
        a5 += v * w5[p];
        a6 += v * w6[p];
    }
    __shared__ float red[3][128];
    red[0][threadIdx.x] = a4;
    red[1][threadIdx.x] = a5;
    red[2][threadIdx.x] = a6;
    __syncthreads();
    for (int s2 = 64; s2 > 0; s2 >>= 1) {
        if (threadIdx.x < s2) {
            red[0][threadIdx.x] += red[0][threadIdx.x + s2];
            red[1][threadIdx.x] += red[1][threadIdx.x + s2];
            red[2][threadIdx.x] += red[2][threadIdx.x + s2];
        }
        __syncthreads();
    }
    if (threadIdx.x == 0) {
        const int o = b * TT + t;
        out[o]          = red[0][0] + b4[lab];
        out[BT + o]     = red[1][0] + b5[lab];
        out[2 * BT + o] = red[2][0] + b6[lab];
    }
}

__global__ void zero_kernel(float* p, int n)
{
    int i = blockIdx.x * blockDim.x + threadIdx.x;
    if (i < n) p[i] = 0.0f;
}

// ---------------------------------------------------------------------------
// Launch
// ---------------------------------------------------------------------------
extern "C" void kernel_launch(void* const* d_in, const int* in_sizes, int n_in,
                              void* d_out, int out_size)
{
    const float* x    = (const float*)d_in[0];
    const int*   labr = (const int*)d_in[1];
    const float* W1   = (const float*)d_in[2];
    const float* b1   = (const float*)d_in[3];
    const float* W2   = (const float*)d_in[4];
    const float* b2   = (const float*)d_in[5];
    const float* W_ih = (const float*)d_in[6];
    const float* W_hh = (const float*)d_in[7];
    const float* b_ih = (const float*)d_in[8];
    const float* b_hh = (const float*)d_in[9];
    const float* W3   = (const float*)d_in[10];
    const float* b3   = (const float*)d_in[11];
    const float* W4   = (const float*)d_in[12];
    const float* b4   = (const float*)d_in[13];
    const float* W5   = (const float*)d_in[14];
    const float* b5   = (const float*)d_in[15];
    const float* W6   = (const float*)d_in[16];
    const float* b6   = (const float*)d_in[17];
    float* out = (float*)d_out;

    float *act1, *act2, *xg, *hs, *outs, *hg, *hhi, *hlo;
    cudaGetSymbolAddress((void**)&act1, g_act1);
    cudaGetSymbolAddress((void**)&act2, g_act2);
    cudaGetSymbolAddress((void**)&xg,   g_xg);
    cudaGetSymbolAddress((void**)&hs,   g_hs);
    cudaGetSymbolAddress((void**)&outs, g_outs);
    cudaGetSymbolAddress((void**)&hg,   g_hg);
    cudaGetSymbolAddress((void**)&hhi,  g_hhi);
    cudaGetSymbolAddress((void**)&hlo,  g_hlo);

    // Labels (dtype-robust)
    decode_labels_kernel<<<1, 64>>>(labr);

    // h0 = 0 (hs slot 0 + hi/lo splits)
    zero_kernel<<<(BB * HM + 255) / 256, 256>>>(hs, BB * HM);
    zero_kernel<<<(BB * HM + 255) / 256, 256>>>(hhi, BB * HM);
    zero_kernel<<<(BB * HM + 255) / 256, 256>>>(hlo, BB * HM);

    const int tail = out_size - 3 * BT;
    if (tail > 0)
        zero_kernel<<<(tail + 255) / 256, 256>>>(out + 3 * BT, tail);

    // act1 = relu(x @ W1^T + b1)   [BT, H1], K=24  (FFMA: K not %32)
    {
        dim3 g(H1 / 128, BT / 128);
        gemm_ffma_nt<<<g, 256>>>(x, W1, b1, act1, BT, H1, INF);
    }
    // act2 = relu(act1 @ W2^T + b2)  [BT, H2], K=1024
    {
        dim3 g(H2 / 128, BT / 128);
        gemm_tf32_nt<true><<<g, 256>>>(act1, W2, b2, act2, BT, H2, H1);
    }
    // xg = act2 @ W_ih^T + b_ih    [BT, 6144], K=2048
    {
        dim3 g(G3 / 128, BT / 128);
        gemm_tf32_nt<false><<<g, 256>>>(act2, W_ih, b_ih, xg, BT, G3, H2);
    }
    // GRU recurrence
    for (int t = 0; t < TT; t++) {
        gru_gemm<<<G3 / 64, 128>>>(hhi, hlo, W_hh, hg);
        gru_fuse<<<(BB * HM) / 256, 256>>>(
            hg, xg, hs + (size_t)t * BB * HM, b_hh,
            hs + (size_t)(t + 1) * BB * HM, hhi, hlo, t);
    }
    // out_s = relu(hs[1..T] @ W3^T + b3)  [BT, PEN], K=2048
    {
        dim3 g(PEN / 128, BT / 128);
        gemm_tf32_nt<true><<<g, 256>>>(hs + (size_t)BB * HM, W3, b3, outs, BT, PEN, H2);
    }
    // heads
    heads_kernel<<<BT, 128>>>(outs, W4, b4, W5, b5, W6, b6, out);
}

// round 4
// speedup vs baseline: 1.4187x; 1.2245x over previous
#include <cuda_runtime.h>
#include <cuda_bf16.h>
#include <math.h>
#include <stdint.h>

// Problem constants
#define BB   64
#define TT   366
#define INF  24
#define H1   1024
#define H2   2048
#define HM   2048
#define PEN  1024
#define BT   23424      // BB*TT
#define G3   6144       // 3*HM
#define NBLK 96         // persistent GRU blocks (co-resident on 148 SMs)

// ---------------------------------------------------------------------------
// Scratch (allocation-free: __device__ globals)
// ---------------------------------------------------------------------------
__device__ float g_act1[(size_t)BT * H1];            //  96 MB
__device__ float g_act2[(size_t)BT * H2];            // 192 MB
__device__ float g_xg  [(size_t)BT * G3];            // 576 MB
__device__ float g_hs  [(size_t)(TT + 1) * BB * HM]; // 192 MB (slot 0 = h0 = 0)
__device__ float g_outs[(size_t)BT * PEN];           //  96 MB
__device__ float g_hg  [(size_t)BB * G3];            // 1.5 MB  gate pre-activations
__device__ __nv_bfloat16 g_hhi[(size_t)BB * HM];     // h split hi (bf16)
__device__ __nv_bfloat16 g_hlo[(size_t)BB * HM];     // h split lo (bf16)
__device__ __nv_bfloat16 g_Whi[(size_t)G3 * HM];     // W_hh split hi (25 MB)
__device__ __nv_bfloat16 g_Wlo[(size_t)G3 * HM];     // W_hh split lo (25 MB)
__device__ int      g_labels[BB];
__device__ unsigned g_bar_cnt = 0;
__device__ volatile unsigned g_bar_gen = 0;

// ---------------------------------------------------------------------------
// mma helpers
// ---------------------------------------------------------------------------
__device__ __forceinline__ unsigned f2tf32(float x) {
    unsigned u;
    asm("cvt.rna.tf32.f32 %0, %1;" : "=r"(u) : "f"(x));
    return u;
}

__device__ __forceinline__ void mma_tf32(float* d, const unsigned* a, const unsigned* b) {
    asm volatile(
        "mma.sync.aligned.m16n8k8.row.col.f32.tf32.tf32.f32 "
        "{%0,%1,%2,%3}, {%4,%5,%6,%7}, {%8,%9}, {%0,%1,%2,%3};"
        : "+f"(d[0]), "+f"(d[1]), "+f"(d[2]), "+f"(d[3])
        : "r"(a[0]), "r"(a[1]), "r"(a[2]), "r"(a[3]), "r"(b[0]), "r"(b[1]));
}

__device__ __forceinline__ void mma_bf16(float* d, const unsigned* a, const unsigned* b) {
    asm volatile(
        "mma.sync.aligned.m16n8k16.row.col.f32.bf16.bf16.f32 "
        "{%0,%1,%2,%3}, {%4,%5,%6,%7}, {%8,%9}, {%0,%1,%2,%3};"
        : "+f"(d[0]), "+f"(d[1]), "+f"(d[2]), "+f"(d[3])
        : "r"(a[0]), "r"(a[1]), "r"(a[2]), "r"(a[3]), "r"(b[0]), "r"(b[1]));
}

#define TKP 36   // padded k-stride (32-bit words): bank = 4*row + kword -> conflict-free

// ---------------------------------------------------------------------------
// Software grid barrier (all NBLK blocks co-resident).
// __threadfence (gpu scope) emits CCTL.IVALL -> L1 coherence across SMs.
// ---------------------------------------------------------------------------
__device__ __forceinline__ void gridbar()
{
    __syncthreads();
    if (threadIdx.x == 0) {
        __threadfence();
        unsigned mygen = g_bar_gen;
        if (atomicAdd(&g_bar_cnt, 1u) == NBLK - 1) {
            g_bar_cnt = 0;
            __threadfence();
            g_bar_gen = mygen + 1;
        } else {
            while (g_bar_gen == mygen) { __nanosleep(32); }
        }
        __threadfence();
    }
    __syncthreads();
}

// ---------------------------------------------------------------------------
// Label decode: dtype-robust (int32 vs int64 little-endian).
// ---------------------------------------------------------------------------
__global__ void decode_labels_kernel(const int* __restrict__ raw)
{
    __shared__ int any_odd_nonzero;
    if (threadIdx.x == 0) any_odd_nonzero = 0;
    __syncthreads();
    if (threadIdx.x < 32) {
        if (raw[2 * threadIdx.x + 1] != 0) atomicOr(&any_odd_nonzero, 1);
    }
    __syncthreads();
    const bool is64 = (any_odd_nonzero == 0);
    if (threadIdx.x < BB) {
        g_labels[threadIdx.x] = is64 ? raw[2 * threadIdx.x] : raw[threadIdx.x];
    }
}

// ---------------------------------------------------------------------------
// W_hh split prep: W -> Whi(bf16) + Wlo(bf16)
// ---------------------------------------------------------------------------
__global__ __launch_bounds__(256) void prep_w_kernel(
    const float* __restrict__ W,
    __nv_bfloat16* __restrict__ Whi, __nv_bfloat16* __restrict__ Wlo, int n)
{
    int i = blockIdx.x * 256 + threadIdx.x;
    if (i < n) {
        float w = W[i];
        __nv_bfloat16 hi = __float2bfloat16(w);
        Whi[i] = hi;
        Wlo[i] = __float2bfloat16(w - __bfloat162float(hi));
    }
}

// ---------------------------------------------------------------------------
// Persistent GRU: all 366 steps in one kernel. 96 blocks x 256 threads.
// Per step: block computes HG[64, 64 cols] = (hhi+hlo) @ (Whi+Wlo)^T slice via
// 3-term split-bf16 mma; gridbar; fused gate update (writes hs[t+1], hhi, hlo);
// gridbar.
// ---------------------------------------------------------------------------
__global__ __launch_bounds__(256) void gru_persist(
    const float* __restrict__ xg,
    const __nv_bfloat16* __restrict__ Whi,
    const __nv_bfloat16* __restrict__ Wlo,
    const float* __restrict__ b_hh,
    float* __restrict__ hs,
    __nv_bfloat16* __restrict__ hhi,
    __nv_bfloat16* __restrict__ hlo,
    float* __restrict__ HG)
{
    __shared__ unsigned sAh[64 * TKP];
    __shared__ unsigned sAl[64 * TKP];
    __shared__ unsigned sBh[64 * TKP];
    __shared__ unsigned sBl[64 * TKP];

    const int tid  = threadIdx.x;
    const int bid  = blockIdx.x;
    const int lane = tid & 31;
    const int warp = tid >> 5;
    const int wm   = warp >> 2;   // 0..1 (32 rows)
    const int wn   = warp & 3;    // 0..3 (16 cols)
    const int g    = lane >> 2;
    const int tg   = lane & 3;
    const int n0   = bid * 64;    // this block's G3 column base

    // init h state = 0
    for (int i = bid * 256 + tid; i < BB * HM; i += NBLK * 256) {
        hs[i]  = 0.0f;
        hhi[i] = __float2bfloat16(0.0f);
        hlo[i] = __float2bfloat16(0.0f);
    }
    gridbar();

    for (int t = 0; t < TT; t++) {
        // ---- recurrent GEMM slice ----
        float acc[2][2][4];
#pragma unroll
        for (int i = 0; i < 2; i++)
#pragma unroll
            for (int j = 0; j < 2; j++)
#pragma unroll
                for (int q = 0; q < 4; q++) acc[i][j][q] = 0.0f;

        uint4 pAh[2], pAl[2], pBh[2], pBl[2];

        // prefetch tile 0
        {
            const int kb = 0;
#pragma unroll
            for (int q = 0; q < 2; q++) {
                const int u4  = tid * 2 + q;      // 0..511
                const int row = u4 >> 3;          // 0..63
                const int off = (u4 & 7) * 8;     // bf16 offset
                pAh[q] = *(const uint4*)(hhi + (size_t)row * HM + kb + off);
                pAl[q] = *(const uint4*)(hlo + (size_t)row * HM + kb + off);
                pBh[q] = *(const uint4*)(Whi + (size_t)(n0 + row) * HM + kb + off);
                pBl[q] = *(const uint4*)(Wlo + (size_t)(n0 + row) * HM + kb + off);
            }
        }

        for (int kt = 0; kt < HM / 64; kt++) {
            __syncthreads();
#pragma unroll
            for (int q = 0; q < 2; q++) {
                const int u4   = tid * 2 + q;
                const int row  = u4 >> 3;
                const int woff = (u4 & 7) * 4;
                *(uint4*)&sAh[row * TKP + woff] = pAh[q];
                *(uint4*)&sAl[row * TKP + woff] = pAl[q];
                *(uint4*)&sBh[row * TKP + woff] = pBh[q];
                *(uint4*)&sBl[row * TKP + woff] = pBl[q];
            }
            __syncthreads();

            if (kt + 1 < HM / 64) {
                const int kb = (kt + 1) * 64;
#pragma unroll
                for (int q = 0; q < 2; q++) {
                    const int u4  = tid * 2 + q;
                    const int row = u4 >> 3;
                    const int off = (u4 & 7) * 8;
                    pAh[q] = *(const uint4*)(hhi + (size_t)row * HM + kb + off);
                    pAl[q] = *(const uint4*)(hlo + (size_t)row * HM + kb + off);
                    pBh[q] = *(const uint4*)(Whi + (size_t)(n0 + row) * HM + kb + off);
                    pBl[q] = *(const uint4*)(Wlo + (size_t)(n0 + row) * HM + kb + off);
                }
            }

#pragma unroll
            for (int kc = 0; kc < 4; kc++) {
                unsigned ah[2][4], al[2][4];
#pragma unroll
                for (int i = 0; i < 2; i++) {
                    const int r0 = (wm * 32 + i * 16 + g) * TKP + kc * 8 + tg;
                    const int r1 = r0 + 8 * TKP;
                    ah[i][0] = sAh[r0]; ah[i][1] = sAh[r1];
                    ah[i][2] = sAh[r0 + 4]; ah[i][3] = sAh[r1 + 4];
                    al[i][0] = sAl[r0]; al[i][1] = sAl[r1];
                    al[i][2] = sAl[r0 + 4]; al[i][3] = sAl[r1 + 4];
                }
                unsigned bh[2][2], bl[2][2];
#pragma unroll
                for (int j = 0; j < 2; j++) {
                    const int r = (wn * 16 + j * 8 + g) * TKP + kc * 8 + tg;
                    bh[j][0] = sBh[r]; bh[j][1] = sBh[r + 4];
                    bl[j][0] = sBl[r]; bl[j][1] = sBl[r + 4];
                }
#pragma unroll
                for (int i = 0; i < 2; i++)
#pragma unroll
                    for (int j = 0; j < 2; j++) {
                        mma_bf16(acc[i][j], ah[i], bh[j]);
                        mma_bf16(acc[i][j], ah[i], bl[j]);
                        mma_bf16(acc[i][j], al[i], bh[j]);
                    }
            }
        }

        // epilogue -> HG
#pragma unroll
        for (int i = 0; i < 2; i++) {
            const int row = wm * 32 + i * 16 + g;
#pragma unroll
            for (int j = 0; j < 2; j++) {
                const int col = n0 + wn * 16 + j * 8 + tg * 2;
                HG[(size_t)row * G3 + col]           = acc[i][j][0];
                HG[(size_t)row * G3 + col + 1]       = acc[i][j][1];
                HG[(size_t)(row + 8) * G3 + col]     = acc[i][j][2];
                HG[(size_t)(row + 8) * G3 + col + 1] = acc[i][j][3];
            }
        }
        gridbar();

        // ---- fused gates ----
        {
            const float* hsp = hs + (size_t)t * (BB * HM);
            float*       hsn = hs + (size_t)(t + 1) * (BB * HM);
            for (int idx = bid * 256 + tid; idx < BB * HM; idx += NBLK * 256) {
                const int b = idx >> 11;
                const int u = idx & 2047;
                const float ar = HG[(size_t)b * G3 + u]          + b_hh[u];
                const float az = HG[(size_t)b * G3 + HM + u]     + b_hh[HM + u];
                const float an = HG[(size_t)b * G3 + 2 * HM + u] + b_hh[2 * HM + u];
                const float* xrow = xg + (size_t)(b * TT + t) * G3;
                const float r  = 1.0f / (1.0f + expf(-(xrow[u] + ar)));
                const float z  = 1.0f / (1.0f + expf(-(xrow[HM + u] + az)));
                const float nn = tanhf(xrow[2 * HM + u] + r * an);
                const float hp = hsp[idx];
                const float h  = (1.0f - z) * nn + z * hp;
                hsn[idx] = h;
                const __nv_bfloat16 hb = __float2bfloat16(h);
                hhi[idx] = hb;
                hlo[idx] = __float2bfloat16(h - __bfloat162float(hb));
            }
        }
        gridbar();
    }
}

// ---------------------------------------------------------------------------
// TF32 tensor-core NT GEMM (unchanged from R3): C = act(A @ B^T + bias)
// ---------------------------------------------------------------------------
template<bool RELU>
__global__ __launch_bounds__(256, 2) void gemm_tf32_nt(
    const float* __restrict__ A, const float* __restrict__ Bm,
    const float* __restrict__ bias, float* __restrict__ C,
    int M, int N, int K)
{
    __shared__ unsigned As[128 * TKP];
    __shared__ unsigned Bs[128 * TKP];

    const int tid  = threadIdx.x;
    const int lane = tid & 31;
    const int warp = tid >> 5;
    const int wm   = warp >> 2;
    const int wn   = warp & 3;
    const int g    = lane >> 2;
    const int tg   = lane & 3;

    const int mBase = blockIdx.y * 128;
    const int nBase = blockIdx.x * 128;
    const int lrow  = tid >> 1;
    const int lcol  = (tid & 1) << 2;

    float acc[4][4][4];
#pragma unroll
    for (int i = 0; i < 4; i++)
#pragma unroll
        for (int j = 0; j < 4; j++)
#pragma unroll
            for (int q = 0; q < 4; q++) acc[i][j][q] = 0.0f;

    const float* Ap = A  + (size_t)(mBase + lrow) * K + lcol;
    const float* Bp = Bm + (size_t)(nBase + lrow) * K + lcol;

    for (int k0 = 0; k0 < K; k0 += 32) {
        __syncthreads();
#pragma unroll
        for (int p = 0; p < 4; p++) {
            float4 av = *(const float4*)(Ap + k0 + p * 8);
            float4 bv = *(const float4*)(Bp + k0 + p * 8);
            uint4 at = make_uint4(f2tf32(av.x), f2tf32(av.y), f2tf32(av.z), f2tf32(av.w));
            uint4 bt = make_uint4(f2tf32(bv.x), f2tf32(bv.y), f2tf32(bv.z), f2tf32(bv.w));
            *(uint4*)&As[lrow * TKP + p * 8 + lcol] = at;
            *(uint4*)&Bs[lrow * TKP + p * 8 + lcol] = bt;
        }
        __syncthreads();
#pragma unroll
        for (int kk = 0; kk < 32; kk += 8) {
            unsigned af[4][4], bf[4][2];
#pragma unroll
            for (int f = 0; f < 4; f++) {
                const int r = (wm * 64 + f * 16 + g) * TKP + kk + tg;
                af[f][0] = As[r];
                af[f][1] = As[r + 8 * TKP];
                af[f][2] = As[r + 4];
                af[f][3] = As[r + 8 * TKP + 4];
            }
#pragma unroll
            for (int f = 0; f < 4; f++) {
                const int r = (wn * 32 + f * 8 + g) * TKP + kk + tg;
                bf[f][0] = Bs[r];
                bf[f][1] = Bs[r + 4];
            }
#pragma unroll
            for (int i = 0; i < 4; i++)
#pragma unroll
                for (int j = 0; j < 4; j++)
                    mma_tf32(acc[i][j], af[i], bf[j]);
        }
    }

#pragma unroll
    for (int i = 0; i < 4; i++) {
        const int row = mBase + wm * 64 + i * 16 + g;
#pragma unroll
        for (int j = 0; j < 4; j++) {
            const int col = nBase + wn * 32 + j * 8 + tg * 2;
            const float b0 = bias[col], b1 = bias[col + 1];
            float v00 = acc[i][j][0] + b0, v01 = acc[i][j][1] + b1;
            float v10 = acc[i][j][2] + b0, v11 = acc[i][j][3] + b1;
            if (RELU) {
                v00 = fmaxf(v00, 0.0f); v01 = fmaxf(v01, 0.0f);
                v10 = fmaxf(v10, 0.0f); v11 = fmaxf(v11, 0.0f);
            }
            C[(size_t)row * N + col]           = v00;
            C[(size_t)row * N + col + 1]       = v01;
            C[(size_t)(row + 8) * N + col]     = v10;
            C[(size_t)(row + 8) * N + col + 1] = v11;
        }
    }
}

// ---------------------------------------------------------------------------
// FFMA GEMM (act1 only, K=24)
// ---------------------------------------------------------------------------
__global__ __launch_bounds__(256) void gemm_ffma_nt(
    const float* __restrict__ A, const float* __restrict__ Bm,
    const float* __restrict__ bias, float* __restrict__ C,
    int M, int N, int K)
{
    __shared__ float As[8][128];
    __shared__ float Bs[8][128];

    const int tid  = threadIdx.x;
    const int tx   = tid & 15;
    const int ty   = tid >> 4;
    const int arow = tid >> 1;
    const int acol = (tid & 1) << 2;

    const float* Ap = A  + (size_t)(blockIdx.y * 128 + arow) * K + acol;
    const float* Bp = Bm + (size_t)(blockIdx.x * 128 + arow) * K + acol;

    float acc[8][8];
#pragma unroll
    for (int i = 0; i < 8; i++)
#pragma unroll
        for (int j = 0; j < 8; j++) acc[i][j] = 0.0f;

    for (int k0 = 0; k0 < K; k0 += 8) {
        float4 a = *(const float4*)(Ap + k0);
        float4 b = *(const float4*)(Bp + k0);
        __syncthreads();
        As[acol + 0][arow] = a.x; As[acol + 1][arow] = a.y;
        As[acol + 2][arow] = a.z; As[acol + 3][arow] = a.w;
        Bs[acol + 0][arow] = b.x; Bs[acol + 1][arow] = b.y;
        Bs[acol + 2][arow] = b.z; Bs[acol + 3][arow] = b.w;
        __syncthreads();
#pragma unroll
        for (int k = 0; k < 8; k++) {
            float av[8], bv[8];
            *(float4*)(av)     = *(const float4*)&As[k][ty * 8];
            *(float4*)(av + 4) = *(const float4*)&As[k][ty * 8 + 4];
            *(float4*)(bv)     = *(const float4*)&Bs[k][tx * 8];
            *(float4*)(bv + 4) = *(const float4*)&Bs[k][tx * 8 + 4];
#pragma unroll
            for (int i = 0; i < 8; i++)
#pragma unroll
                for (int j = 0; j < 8; j++)
                    acc[i][j] += av[i] * bv[j];
        }
    }

    const int crow = blockIdx.y * 128 + ty * 8;
    const int ccol = blockIdx.x * 128 + tx * 8;
#pragma unroll
    for (int i = 0; i < 8; i++) {
#pragma unroll
        for (int j = 0; j < 8; j++) {
            float v = acc[i][j] + bias[ccol + j];
            v = fmaxf(v, 0.0f);
            C[(size_t)(crow + i) * N + ccol + j] = v;
        }
    }
}

// ---------------------------------------------------------------------------
// Per-(b,t) heads
// ---------------------------------------------------------------------------
__global__ __launch_bounds__(128) void heads_kernel(
    const float* __restrict__ outs,
    const float* __restrict__ W4, const float* __restrict__ b4,
    const float* __restrict__ W5, const float* __restrict__ b5,
    const float* __restrict__ W6, const float* __restrict__ b6,
    float* __restrict__ out)
{
    const int r  = blockIdx.x;     // t*BB + b
    const int t  = r >> 6;
    const int b  = r & 63;
    const int lab = g_labels[b];
    const float* s  = outs + (size_t)r * PEN;
    const float* w4 = W4 + (size_t)lab * PEN;
    const float* w5 = W5 + (size_t)lab * PEN;
    const float* w6 = W6 + (size_t)lab * PEN;

    float a4 = 0.f, a5 = 0.f, a6 = 0.f;
    for (int p = threadIdx.x; p < PEN; p += 128) {
        const float v = s[p];
        a4 += v * w4[p];
        a5 += v * w5[p];
        a6 += v * w6[p];
    }
    __shared__ float red[3][128];
    red[0][threadIdx.x] = a4;
    red[1][threadIdx.x] = a5;
    red[2][threadIdx.x] = a6;
    __syncthreads();
    for (int s2 = 64; s2 > 0; s2 >>= 1) {
        if (threadIdx.x < s2) {
            red[0][threadIdx.x] += red[0][threadIdx.x + s2];
            red[1][threadIdx.x] += red[1][threadIdx.x + s2];
            red[2][threadIdx.x] += red[2][threadIdx.x + s2];
        }
        __syncthreads();
    }
    if (threadIdx.x == 0) {
        const int o = b * TT + t;
        out[o]          = red[0][0] + b4[lab];
        out[BT + o]     = red[1][0] + b5[lab];
        out[2 * BT + o] = red[2][0] + b6[lab];
    }
}

__global__ void zero_kernel(float* p, int n)
{
    int i = blockIdx.x * blockDim.x + threadIdx.x;
    if (i < n) p[i] = 0.0f;
}

// ---------------------------------------------------------------------------
// Launch
// ---------------------------------------------------------------------------
extern "C" void kernel_launch(void* const* d_in, const int* in_sizes, int n_in,
                              void* d_out, int out_size)
{
    const float* x    = (const float*)d_in[0];
    const int*   labr = (const int*)d_in[1];
    const float* W1   = (const float*)d_in[2];
    const float* b1   = (const float*)d_in[3];
    const float* W2   = (const float*)d_in[4];
    const float* b2   = (const float*)d_in[5];
    const float* W_ih = (const float*)d_in[6];
    const float* W_hh = (const float*)d_in[7];
    const float* b_ih = (const float*)d_in[8];
    const float* b_hh = (const float*)d_in[9];
    const float* W3   = (const float*)d_in[10];
    const float* b3   = (const float*)d_in[11];
    const float* W4   = (const float*)d_in[12];
    const float* b4   = (const float*)d_in[13];
    const float* W5   = (const float*)d_in[14];
    const float* b5   = (const float*)d_in[15];
    const float* W6   = (const float*)d_in[16];
    const float* b6   = (const float*)d_in[17];
    float* out = (float*)d_out;

    float *act1, *act2, *xg, *hs, *outs, *hg;
    __nv_bfloat16 *hhi, *hlo, *whi, *wlo;
    cudaGetSymbolAddress((void**)&act1, g_act1);
    cudaGetSymbolAddress((void**)&act2, g_act2);
    cudaGetSymbolAddress((void**)&xg,   g_xg);
    cudaGetSymbolAddress((void**)&hs,   g_hs);
    cudaGetSymbolAddress((void**)&outs, g_outs);
    cudaGetSymbolAddress((void**)&hg,   g_hg);
    cudaGetSymbolAddress((void**)&hhi,  g_hhi);
    cudaGetSymbolAddress((void**)&hlo,  g_hlo);
    cudaGetSymbolAddress((void**)&whi,  g_Whi);
    cudaGetSymbolAddress((void**)&wlo,  g_Wlo);

    // 1) act1 = relu(x @ W1^T + b1)   [BT, H1], K=24  (FFMA)
    {
        dim3 g(H1 / 128, BT / 128);
        gemm_ffma_nt<<<g, 256>>>(x, W1, b1, act1, BT, H1, INF);
    }
    // 2) act2 = relu(act1 @ W2^T + b2)  [BT, H2]
    {
        dim3 g(H2 / 128, BT / 128);
        gemm_tf32_nt<true><<<g, 256>>>(act1, W2, b2, act2, BT, H2, H1);
    }
    // 3) xg = act2 @ W_ih^T + b_ih    [BT, 6144]
    {
        dim3 g(G3 / 128, BT / 128);
        gemm_tf32_nt<false><<<g, 256>>>(act2, W_ih, b_ih, xg, BT, G3, H2);
    }
    // 4) W_hh split prep
    prep_w_kernel<<<(G3 * HM + 255) / 256, 256>>>(W_hh, whi, wlo, G3 * HM);
    // 5) labels
    decode_labels_kernel<<<1, 64>>>(labr);
    // 6) persistent GRU (ncu -s 5 captures this launch)
    gru_persist<<<NBLK, 256>>>(xg, whi, wlo, b_hh, hs, hhi, hlo, hg);
    // 7) out_s = relu(hs[1..T] @ W3^T + b3)  [BT, PEN]
    {
        dim3 g(PEN / 128, BT / 128);
        gemm_tf32_nt<true><<<g, 256>>>(hs + (size_t)BB * HM, W3, b3, outs, BT, PEN, H2);
    }
    // 8) heads
    heads_kernel<<<BT, 128>>>(outs, W4, b4, W5, b5, W6, b6, out);
    // 9) zero tail of d_out (the two scalar 0 outputs, if present)
    const int tail = out_size - 3 * BT;
    if (tail > 0)
        zero_kernel<<<(tail + 255) / 256, 256>>>(out + 3 * BT, tail);
}